// round 8
// baseline (speedup 1.0000x reference)
#include <cuda_runtime.h>
#include <cuda_fp16.h>
#include <cstdint>

// QuantizedLinear: out[N,OUT] = x[N,IN] @ dequant(w_packed)^T + bias
//   W[o,i] = (nib(o,i)-8)*scale[o]; w_packed int32 has ONE byte payload.
//
// int8 dual-GEMM probe: x -> 15-bit fixed point m = h*128 + l (per-row scale
// s_n), exact integer GEMMs via mma.sync.m16n8k32.s32.s8.u8.s32 against raw
// u8 nibbles q. y = scale_o*(s_n*(128*aH + aL) - 8*s_n*sum(m)) + bias_o.

#define NR 4096
#define KD 4096
#define OD 4096
#define BM 128
#define BN 64
#define BK 32
#define NIT (KD / BK)
#define NSTG 4

#define A_STRIDE 48                       // 32B data + 16B pad (bank-clean)
#define A_BYTES  (BM * A_STRIDE)          // 6144
#define B_OFF    (2 * A_BYTES)            // 12288
#define STG_SZ   (B_OFF + BN * 16)        // 13312
#define SM_TOT   (NSTG * STG_SZ)          // 53248 (dynamic)

__device__ int8_t  g_h[(size_t)NR * KD];
__device__ int8_t  g_l[(size_t)NR * KD];
__device__ uint8_t g_wb[(size_t)OD * (KD / 2)];
__device__ float   g_r1[NR];              // s_n
__device__ float   g_rS[NR];              // 8 * s_n * sum(m)

__device__ __forceinline__ uint32_t s2u(const void* p) {
    uint32_t a;
    asm("{ .reg .u64 t; cvta.to.shared.u64 t, %1; cvt.u32.u64 %0, t; }"
        : "=r"(a) : "l"(p));
    return a;
}

#define CP16(dst, src) \
    asm volatile("cp.async.cg.shared.global [%0], [%1], 16;" \
                 :: "r"(dst), "l"(src) : "memory")
#define CPCOMMIT() asm volatile("cp.async.commit_group;" ::: "memory")
#define CPWAIT2()  asm volatile("cp.async.wait_group 2;"  ::: "memory")

__device__ __forceinline__ void imma(int* c, const uint32_t* a,
                                     uint32_t b0, uint32_t b1) {
    asm volatile(
        "mma.sync.aligned.m16n8k32.row.col.s32.s8.u8.s32 "
        "{%0,%1,%2,%3}, {%4,%5,%6,%7}, {%8,%9}, {%0,%1,%2,%3};"
        : "+r"(c[0]), "+r"(c[1]), "+r"(c[2]), "+r"(c[3])
        : "r"(a[0]), "r"(a[1]), "r"(a[2]), "r"(a[3]), "r"(b0), "r"(b1));
}

// ---- pre-pass: per-row 15-bit quantize of x ----
__global__ void quant_x(const float* __restrict__ x) {
    __shared__ float smax[4];
    __shared__ int   ssum[4];
    __shared__ float sinv;
    const int n = blockIdx.x, t = threadIdx.x;   // 128 threads
    const float* xr = x + (size_t)n * KD;

    float mx = 0.0f;
#pragma unroll
    for (int j = 0; j < 8; j++) {
        float4 v = *(const float4*)(xr + t * 32 + j * 4);
        mx = fmaxf(mx, fmaxf(fmaxf(fabsf(v.x), fabsf(v.y)),
                             fmaxf(fabsf(v.z), fabsf(v.w))));
    }
#pragma unroll
    for (int o = 16; o > 0; o >>= 1)
        mx = fmaxf(mx, __shfl_xor_sync(0xFFFFFFFFu, mx, o));
    if ((t & 31) == 0) smax[t >> 5] = mx;
    __syncthreads();
    if (t == 0) {
        float m = fmaxf(fmaxf(smax[0], smax[1]), fmaxf(smax[2], smax[3]));
        sinv = (m > 1e-30f) ? (16319.0f / m) : 0.0f;
        g_r1[n] = (m > 1e-30f) ? (m / 16319.0f) : 0.0f;
    }
    __syncthreads();
    const float inv = sinv;

    int rowsum = 0;
#pragma unroll
    for (int j = 0; j < 8; j++) {
        float4 v = *(const float4*)(xr + t * 32 + j * 4);
        int m0 = __float2int_rn(v.x * inv), m1 = __float2int_rn(v.y * inv);
        int m2 = __float2int_rn(v.z * inv), m3 = __float2int_rn(v.w * inv);
        rowsum += m0 + m1 + m2 + m3;
        int h0 = (m0 + 64) >> 7, h1 = (m1 + 64) >> 7;
        int h2 = (m2 + 64) >> 7, h3 = (m3 + 64) >> 7;
        int l0 = m0 - (h0 << 7), l1 = m1 - (h1 << 7);
        int l2 = m2 - (h2 << 7), l3 = m3 - (h3 << 7);
        uint32_t hw = (uint32_t)(h0 & 0xFF) | ((uint32_t)(h1 & 0xFF) << 8) |
                      ((uint32_t)(h2 & 0xFF) << 16) | ((uint32_t)h3 << 24);
        uint32_t lw = (uint32_t)(l0 & 0xFF) | ((uint32_t)(l1 & 0xFF) << 8) |
                      ((uint32_t)(l2 & 0xFF) << 16) | ((uint32_t)l3 << 24);
        size_t wi = ((size_t)n * KD + t * 32) / 4 + j;
        ((uint32_t*)g_h)[wi] = hw;
        ((uint32_t*)g_l)[wi] = lw;
    }
#pragma unroll
    for (int o = 16; o > 0; o >>= 1)
        rowsum += __shfl_xor_sync(0xFFFFFFFFu, rowsum, o);
    if ((t & 31) == 0) ssum[t >> 5] = rowsum;
    __syncthreads();
    if (t == 0) {
        int rs = ssum[0] + ssum[1] + ssum[2] + ssum[3];
        g_rS[n] = 8.0f * g_r1[n] * (float)rs;
    }
}

// w_packed int32 (one byte payload each) -> dense uint8
__global__ void repack_w(const int* __restrict__ wp) {
    size_t i = ((size_t)blockIdx.x * 256 + threadIdx.x) * 16;
    const int4* src = (const int4*)(wp + i);
    uint4 o;
    int4 v0 = src[0], v1 = src[1], v2 = src[2], v3 = src[3];
    o.x = (uint32_t)(v0.x & 0xFF) | ((uint32_t)(v0.y & 0xFF) << 8) |
          ((uint32_t)(v0.z & 0xFF) << 16) | ((uint32_t)v0.w << 24);
    o.y = (uint32_t)(v1.x & 0xFF) | ((uint32_t)(v1.y & 0xFF) << 8) |
          ((uint32_t)(v1.z & 0xFF) << 16) | ((uint32_t)v1.w << 24);
    o.z = (uint32_t)(v2.x & 0xFF) | ((uint32_t)(v2.y & 0xFF) << 8) |
          ((uint32_t)(v2.z & 0xFF) << 16) | ((uint32_t)v2.w << 24);
    o.w = (uint32_t)(v3.x & 0xFF) | ((uint32_t)(v3.y & 0xFF) << 8) |
          ((uint32_t)(v3.z & 0xFF) << 16) | ((uint32_t)v3.w << 24);
    *(uint4*)(g_wb + i) = o;
}

extern __shared__ char smem[];

__global__ void __launch_bounds__(256, 2)
qimma_kernel(const float* __restrict__ wscale,
             const float* __restrict__ wbias, float* __restrict__ out)
{
    const int t   = threadIdx.x;
    const int wid = t >> 5, lid = t & 31;
    const int wm  = wid >> 1;            // 0..3 -> m offset wm*32
    const int wn  = wid & 1;             // 0..1 -> n offset wn*32
    const int g   = lid >> 2;            // 0..7
    const int c   = lid & 3;             // 0..3
    const int o0  = blockIdx.x * BN;
    const int n0  = blockIdx.y * BM;
    const uint32_t sb = s2u(smem);
    const uint32_t p  = 2u * (uint32_t)c;
    const uint32_t sel = p | (p << 4) | ((p + 1) << 8) | ((p + 1) << 12);

    const int8_t*  gh = g_h + (size_t)n0 * KD;
    const int8_t*  gl = g_l + (size_t)n0 * KD;
    const uint8_t* wg = g_wb + (size_t)o0 * (KD / 2);

    int accH[2][4][4], accL[2][4][4];
#pragma unroll
    for (int mi = 0; mi < 2; mi++)
#pragma unroll
        for (int nj = 0; nj < 4; nj++)
#pragma unroll
            for (int r = 0; r < 4; r++) {
                accH[mi][nj][r] = 0; accL[mi][nj][r] = 0;
            }

    auto issue = [&](int s, int k0) {
        uint32_t sa = sb + s * STG_SZ;
        int r = t >> 1, ch = (t & 1) * 16;
        CP16(sa + r * A_STRIDE + ch,           gh + (size_t)r * KD + k0 + ch);
        CP16(sa + A_BYTES + r * A_STRIDE + ch, gl + (size_t)r * KD + k0 + ch);
        if (t < BN)
            CP16(sa + B_OFF + t * 16, wg + (size_t)t * (KD / 2) + (k0 >> 1));
    };

#pragma unroll
    for (int s = 0; s < NSTG - 1; s++) { issue(s, s * BK); CPCOMMIT(); }

#pragma unroll 1
    for (int i = 0; i < NIT; i++) {
        CPWAIT2();
        __syncthreads();

        const uint32_t A  = sb + (i & (NSTG - 1)) * STG_SZ;
        const uint32_t Bb = A + B_OFF;

        // B fragments: raw u8 nibbles q, k-ordered via PRMT + mask
        uint32_t bf[4][2];
#pragma unroll
        for (int nj = 0; nj < 4; nj++) {
            int row = wn * 32 + nj * 8 + g;
            uint4 w;
            asm volatile("ld.shared.v4.u32 {%0,%1,%2,%3}, [%4];"
                         : "=r"(w.x), "=r"(w.y), "=r"(w.z), "=r"(w.w)
                         : "r"(Bb + row * 16));
            uint32_t t0 = __byte_perm(w.x, w.y, sel);
            uint32_t t1 = __byte_perm(w.z, w.w, sel);
            bf[nj][0] = (t0 & 0x000F000Fu) | ((t0 >> 4) & 0x0F000F00u);
            bf[nj][1] = (t1 & 0x000F000Fu) | ((t1 >> 4) & 0x0F000F00u);
        }

#pragma unroll
        for (int mi = 0; mi < 2; mi++) {
            uint32_t bh = A + (wm * 32 + mi * 16 + g) * A_STRIDE + c * 4;
            uint32_t ah[4], al[4];
            asm volatile("ld.shared.b32 %0, [%1];" : "=r"(ah[0]) : "r"(bh));
            asm volatile("ld.shared.b32 %0, [%1];" : "=r"(ah[1]) : "r"(bh + 8 * A_STRIDE));
            asm volatile("ld.shared.b32 %0, [%1];" : "=r"(ah[2]) : "r"(bh + 16));
            asm volatile("ld.shared.b32 %0, [%1];" : "=r"(ah[3]) : "r"(bh + 8 * A_STRIDE + 16));
            asm volatile("ld.shared.b32 %0, [%1];" : "=r"(al[0]) : "r"(bh + A_BYTES));
            asm volatile("ld.shared.b32 %0, [%1];" : "=r"(al[1]) : "r"(bh + A_BYTES + 8 * A_STRIDE));
            asm volatile("ld.shared.b32 %0, [%1];" : "=r"(al[2]) : "r"(bh + A_BYTES + 16));
            asm volatile("ld.shared.b32 %0, [%1];" : "=r"(al[3]) : "r"(bh + A_BYTES + 8 * A_STRIDE + 16));
#pragma unroll
            for (int nj = 0; nj < 4; nj++) {
                imma(accH[mi][nj], ah, bf[nj][0], bf[nj][1]);
                imma(accL[mi][nj], al, bf[nj][0], bf[nj][1]);
            }
        }
        __syncthreads();

        int nx = i + NSTG - 1;
        if (nx < NIT) issue(nx & (NSTG - 1), nx * BK);
        CPCOMMIT();
    }

    // ---- epilogue: y = scale_o*(s_n*T - rS_n) + bias_o, T = 128*aH + aL ----
#pragma unroll
    for (int nj = 0; nj < 4; nj++) {
        int col = o0 + wn * 32 + nj * 8 + c * 2;
        float s0 = __ldg(wscale + col), s1 = __ldg(wscale + col + 1);
        float b0 = __ldg(wbias + col),  b1 = __ldg(wbias + col + 1);
#pragma unroll
        for (int mi = 0; mi < 2; mi++) {
#pragma unroll
            for (int half = 0; half < 2; half++) {
                int row = n0 + wm * 32 + mi * 16 + half * 8 + g;
                float r1 = __ldg(g_r1 + row), rS = __ldg(g_rS + row);
                float T0 = __int2float_rn(128 * accH[mi][nj][2 * half]     + accL[mi][nj][2 * half]);
                float T1 = __int2float_rn(128 * accH[mi][nj][2 * half + 1] + accL[mi][nj][2 * half + 1]);
                float2 v;
                v.x = fmaf(s0, fmaf(r1, T0, -rS), b0);
                v.y = fmaf(s1, fmaf(r1, T1, -rS), b1);
                *(float2*)(out + (size_t)row * OD + col) = v;
            }
        }
    }
}

extern "C" void kernel_launch(void* const* d_in, const int* in_sizes, int n_in,
                              void* d_out, int out_size)
{
    const float* x      = (const float*)d_in[0];
    const int*   wpk    = (const int*)  d_in[1];
    const float* wscale = (const float*)d_in[2];
    const float* wbias  = (const float*)d_in[3];
    float*       out    = (float*)d_out;

    cudaFuncSetAttribute(qimma_kernel,
                         cudaFuncAttributeMaxDynamicSharedMemorySize, SM_TOT);

    quant_x<<<NR, 128>>>(x);
    repack_w<<<((size_t)OD * (KD / 2)) / 4096, 256>>>(wpk);

    dim3 grid(OD / BN, NR / BM);
    qimma_kernel<<<grid, 256, SM_TOT>>>(wscale, wbias, out);
}

// round 9
// speedup vs baseline: 3.1567x; 3.1567x over previous
#include <cuda_runtime.h>
#include <cuda_fp16.h>
#include <cstdint>

// QuantizedLinear: out[N,OUT] = x[N,IN] @ dequant(w_packed)^T + bias
//   W[o,i] = (nib(o,i)-8)*scale[o]; w_packed int32 has ONE byte payload.
//
// Legacy HMMA mma.sync.m16n8k16 (f32 acc) at the sm_103 legacy-tensor
// ceiling. R8: BN=64 fine-grain tiles (2048 CTAs -> kills wave
// quantization), single __syncthreads per iter, fused pre-pass.

#define NR 4096
#define KD 4096
#define OD 4096
#define BM 128
#define BN 64
#define BK 32
#define NIT (KD / BK)
#define NSTG 4

#define A_STRIDE 80
#define A_BYTES  (BM * A_STRIDE)        // 10240
#define STG_STR  (A_BYTES + BN * 16)    // 11264
// 4*11264 = 45056 bytes static smem, 2 CTAs/SM

__device__ __half   g_xh[(size_t)NR * KD];
__device__ uint8_t  g_wb[(size_t)OD * (KD / 2)];

__device__ __forceinline__ uint32_t s2u(const void* p) {
    uint32_t a;
    asm("{ .reg .u64 t; cvta.to.shared.u64 t, %1; cvt.u32.u64 %0, t; }"
        : "=r"(a) : "l"(p));
    return a;
}

#define CP16(dst, src) \
    asm volatile("cp.async.cg.shared.global [%0], [%1], 16;" \
                 :: "r"(dst), "l"(src) : "memory")
#define CPCOMMIT() asm volatile("cp.async.commit_group;" ::: "memory")
#define CPWAIT2()  asm volatile("cp.async.wait_group 2;"  ::: "memory")

// packed byte (2 nibbles) -> half2 (lo-8, hi-8), exact.
__device__ __forceinline__ uint32_t nib2h(uint32_t w, uint32_t sel) {
    uint32_t d = __byte_perm(w, 0, sel);            // [b, 0, b, 0]
    d = (d & 0x0000000Fu) | ((d >> 4) & 0x000F0000u) | 0x64006400u;
    const uint32_t C = 0x64086408u;
    __half2 h = __hsub2(*reinterpret_cast<__half2*>(&d),
                        *reinterpret_cast<const __half2*>(&C));
    return *reinterpret_cast<uint32_t*>(&h);
}

__device__ __forceinline__ void mma16816(float* c, const uint32_t* a,
                                         uint32_t b0, uint32_t b1) {
    asm volatile(
        "mma.sync.aligned.m16n8k16.row.col.f32.f16.f16.f32 "
        "{%0,%1,%2,%3}, {%4,%5,%6,%7}, {%8,%9}, {%0,%1,%2,%3};"
        : "+f"(c[0]), "+f"(c[1]), "+f"(c[2]), "+f"(c[3])
        : "r"(a[0]), "r"(a[1]), "r"(a[2]), "r"(a[3]), "r"(b0), "r"(b1));
}

// fused pre-pass: blocks [0,16384) convert x fp32->fp16;
// blocks [16384,18432) repack w int32(byte payload)->uint8.
#define XBLKS 16384
__global__ void prepass(const float* __restrict__ x, const int* __restrict__ wp) {
    if (blockIdx.x < XBLKS) {
        size_t i = ((size_t)blockIdx.x * 256 + threadIdx.x) * 4;
        float4 v = *(const float4*)(x + i);
        *(__half2*)(g_xh + i)     = __floats2half2_rn(v.x, v.y);
        *(__half2*)(g_xh + i + 2) = __floats2half2_rn(v.z, v.w);
    } else {
        size_t i = ((size_t)(blockIdx.x - XBLKS) * 256 + threadIdx.x) * 16;
        const int4* src = (const int4*)(wp + i);
        uint4 o;
        int4 v0 = src[0], v1 = src[1], v2 = src[2], v3 = src[3];
        o.x = (uint32_t)(v0.x & 0xFF) | ((uint32_t)(v0.y & 0xFF) << 8) |
              ((uint32_t)(v0.z & 0xFF) << 16) | ((uint32_t)v0.w << 24);
        o.y = (uint32_t)(v1.x & 0xFF) | ((uint32_t)(v1.y & 0xFF) << 8) |
              ((uint32_t)(v1.z & 0xFF) << 16) | ((uint32_t)v1.w << 24);
        o.z = (uint32_t)(v2.x & 0xFF) | ((uint32_t)(v2.y & 0xFF) << 8) |
              ((uint32_t)(v2.z & 0xFF) << 16) | ((uint32_t)v2.w << 24);
        o.w = (uint32_t)(v3.x & 0xFF) | ((uint32_t)(v3.y & 0xFF) << 8) |
              ((uint32_t)(v3.z & 0xFF) << 16) | ((uint32_t)v3.w << 24);
        *(uint4*)(g_wb + i) = o;
    }
}

__global__ void __launch_bounds__(256, 2)
qmma_kernel(const float* __restrict__ wscale,
            const float* __restrict__ wbias, float* __restrict__ out)
{
    __shared__ __align__(16) char sm[NSTG * STG_STR];

    const int t   = threadIdx.x;
    const int wid = t >> 5, lid = t & 31;
    const int wm  = wid >> 1;            // 0..3 -> m offset wm*32
    const int wn  = wid & 1;             // 0..1 -> n offset wn*32
    const int g   = lid >> 2;            // 0..7
    const int c   = lid & 3;             // 0..3
    const int o0  = blockIdx.x * BN;
    const int n0  = blockIdx.y * BM;
    const uint32_t sb = s2u(sm);
    const uint32_t sel = 0x4040u | ((uint32_t)c << 8) | (uint32_t)c;

    const __half*  xg = g_xh + (size_t)n0 * KD;
    const uint8_t* wg = g_wb + (size_t)o0 * (KD / 2);

    float acc[2][4][4];
#pragma unroll
    for (int mi = 0; mi < 2; mi++)
#pragma unroll
        for (int nj = 0; nj < 4; nj++)
#pragma unroll
            for (int r = 0; r < 4; r++)
                acc[mi][nj][r] = 0.0f;

    auto issue = [&](int s, int k0) {
        uint32_t sa = sb + s * STG_STR;
#pragma unroll
        for (int j = 0; j < 2; j++) {
            int idx = t + j * 256;           // 0..511
            int r = idx >> 2, cc = idx & 3;  // row, 16B-chunk
            CP16(sa + r * A_STRIDE + cc * 16,
                 xg + (size_t)r * KD + k0 + cc * 8);
        }
        if (t < BN)
            CP16(sa + A_BYTES + t * 16, wg + (size_t)t * (KD / 2) + (k0 >> 1));
    };

#pragma unroll
    for (int s = 0; s < NSTG - 1; s++) { issue(s, s * BK); CPCOMMIT(); }

#pragma unroll 1
    for (int i = 0; i < NIT; i++) {
        CPWAIT2();
        __syncthreads();

        // issue stage i+3 into buffer (i-1)&3 (all reads done per top sync)
        int nx = i + NSTG - 1;
        if (nx < NIT) issue(nx & (NSTG - 1), nx * BK);
        CPCOMMIT();

        const uint32_t A  = sb + (i & (NSTG - 1)) * STG_STR;
        const uint32_t Bb = A + A_BYTES;

        uint32_t breg[2][4][2];
#pragma unroll
        for (int nj = 0; nj < 4; nj++) {
            int row = wn * 32 + nj * 8 + g;
            uint4 w;
            asm volatile("ld.shared.v4.u32 {%0,%1,%2,%3}, [%4];"
                         : "=r"(w.x), "=r"(w.y), "=r"(w.z), "=r"(w.w)
                         : "r"(Bb + row * 16));
            breg[0][nj][0] = nib2h(w.x, sel);
            breg[0][nj][1] = nib2h(w.y, sel);
            breg[1][nj][0] = nib2h(w.z, sel);
            breg[1][nj][1] = nib2h(w.w, sel);
        }

#pragma unroll
        for (int ks = 0; ks < 2; ks++) {
#pragma unroll
            for (int mi = 0; mi < 2; mi++) {
                int row = wm * 32 + mi * 16 + g;
                uint32_t base = A + row * A_STRIDE + ks * 32 + c * 4;
                uint32_t a[4];
                asm volatile("ld.shared.b32 %0, [%1];" : "=r"(a[0]) : "r"(base));
                asm volatile("ld.shared.b32 %0, [%1];" : "=r"(a[1]) : "r"(base + 8 * A_STRIDE));
                asm volatile("ld.shared.b32 %0, [%1];" : "=r"(a[2]) : "r"(base + 16));
                asm volatile("ld.shared.b32 %0, [%1];" : "=r"(a[3]) : "r"(base + 8 * A_STRIDE + 16));
#pragma unroll
                for (int nj = 0; nj < 4; nj++)
                    mma16816(acc[mi][nj], a, breg[ks][nj][0], breg[ks][nj][1]);
            }
        }
    }

    // ---- epilogue: scale/bias, direct float2 stores ----
#pragma unroll
    for (int nj = 0; nj < 4; nj++) {
        int col = o0 + wn * 32 + nj * 8 + c * 2;
        float s0 = __ldg(wscale + col), s1 = __ldg(wscale + col + 1);
        float b0 = __ldg(wbias + col),  b1 = __ldg(wbias + col + 1);
#pragma unroll
        for (int mi = 0; mi < 2; mi++) {
            int row = n0 + wm * 32 + mi * 16 + g;
            float2 v0, v1;
            v0.x = fmaf(acc[mi][nj][0], s0, b0);
            v0.y = fmaf(acc[mi][nj][1], s1, b1);
            v1.x = fmaf(acc[mi][nj][2], s0, b0);
            v1.y = fmaf(acc[mi][nj][3], s1, b1);
            *(float2*)(out + (size_t)row * OD + col)       = v0;
            *(float2*)(out + (size_t)(row + 8) * OD + col) = v1;
        }
    }
}

extern "C" void kernel_launch(void* const* d_in, const int* in_sizes, int n_in,
                              void* d_out, int out_size)
{
    const float* x      = (const float*)d_in[0];
    const int*   wpk    = (const int*)  d_in[1];
    const float* wscale = (const float*)d_in[2];
    const float* wbias  = (const float*)d_in[3];
    float*       out    = (float*)d_out;

    prepass<<<XBLKS + 2048, 256>>>(x, wpk);

    dim3 grid(OD / BN, NR / BM);
    qmma_kernel<<<grid, 256>>>(wscale, wbias, out);
}